// round 4
// baseline (speedup 1.0000x reference)
#include <cuda_runtime.h>
#include <math.h>
#include <stdint.h>

#define BB 8
#define TT 32
#define NN 1024
#define DIN 64
#define DR 128
#define DT_VAL 0.25f
#define KC 32
#define NCHUNK (NN / KC)
#define WSLOT (192 * 128)
#define TST 196            // Ts smem stride (>=192, ==4 mod 32)

// ---------------- device scratch ----------------
__device__ float g_h  [BB * NN * DR];    // fp32 recurrent state
__device__ float g_hv1[BB * NN * DR];    // fp32 pre-GRU state (output head src)
__device__ float g_z  [BB * NN * DR];    // fp32 z gate
__device__ float g_obs[BB * TT];
__device__ float g_Atf[BB * NN * NN];    // tf32 A
__device__ float g_Wtf[6 * WSLOT];       // tf32 weights
__device__ float g_Bh [BB * NN * DR];    // tf32 h   (B operand)
__device__ float g_Bu1[BB * NN * DR];    // tf32 u1
__device__ float g_Bu2[BB * NN * DR];    // tf32 u2
__device__ float g_B1 [BB * NN * 192];   // tf32 [x*m | hv1]
__device__ float g_B2 [BB * NN * DR];    // tf32 r*hv1
__device__ float g_Tx [BB * NN * 64];    // tf32 A@(x*m)

// ---------------- helpers ----------------
__device__ __forceinline__ float tf32r(float x) {
    uint32_t u; asm("cvt.rna.tf32.f32 %0, %1;" : "=r"(u) : "f"(x));
    return __uint_as_float(u);
}
__device__ __forceinline__ void cpa16(float* s, const float* g) {
    uint32_t sa = (uint32_t)__cvta_generic_to_shared(s);
    asm volatile("cp.async.cg.shared.global [%0], [%1], 16;" :: "r"(sa), "l"(g));
}
#define MMA_TF32(acc, a, b) \
    asm volatile( \
        "mma.sync.aligned.m16n8k8.row.col.f32.tf32.tf32.f32 " \
        "{%0,%1,%2,%3}, {%4,%5,%6,%7}, {%8,%9}, {%0,%1,%2,%3};" \
        : "+f"((acc)[0]), "+f"((acc)[1]), "+f"((acc)[2]), "+f"((acc)[3]) \
        : "r"((a)[0]), "r"((a)[1]), "r"((a)[2]), "r"((a)[3]), \
          "r"((b)[0]), "r"((b)[1]))

// ---------------- init h = broadcast(h0) (fp32 + tf32 copy) --------------
__global__ void init_h_kernel(const float* __restrict__ h0) {
    int idx = blockIdx.x * blockDim.x + threadIdx.x;
    const int total = BB * NN * DR;
    for (; idx < total; idx += gridDim.x * blockDim.x) {
        float v = h0[idx & (DR - 1)];
        g_h[idx]  = v;
        g_Bh[idx] = tf32r(v);
    }
}

// ---------------- round A to tf32 once ----------------
__global__ void round_A_kernel(const float* __restrict__ A) {
    int idx = blockIdx.x * blockDim.x + threadIdx.x;
    const int total = BB * NN * NN;
    for (; idx < total; idx += gridDim.x * blockDim.x)
        g_Atf[idx] = tf32r(A[idx]);
}

// ---------------- round weights to tf32 once ----------------
// slots: 0 W0 1 W1 2 Wout (128x128)  3 Wz 4 Wr 5 Wh (192x128)
__global__ void round_W_kernel(
    const float* __restrict__ W0, const float* __restrict__ W1,
    const float* __restrict__ Wout, const float* __restrict__ Wz,
    const float* __restrict__ Wr, const float* __restrict__ Wh)
{
    const float* srcs[6] = {W0, W1, Wout, Wz, Wr, Wh};
    const int sizes[6] = {128*128, 128*128, 128*128, 192*128, 192*128, 192*128};
    for (int s = 0; s < 6; s++) {
        const float* src = srcs[s];
        float* dst = g_Wtf + s * WSLOT;
        for (int i = blockIdx.x * blockDim.x + threadIdx.x; i < sizes[s];
             i += gridDim.x * blockDim.x)
            dst[i] = tf32r(src[i]);
    }
}

// ---------------- obs[b,t] ----------------
__global__ void obs_kernel(const float* __restrict__ masks) {
    int bt = blockIdx.x;
    const float* m = masks + (size_t)bt * NN * DIN;
    float s = 0.f;
    for (int i = threadIdx.x; i < NN * DIN / 4; i += blockDim.x) {
        float4 v = ((const float4*)m)[i];
        s += fabsf(v.x) + fabsf(v.y) + fabsf(v.z) + fabsf(v.w);
    }
    __shared__ float red[256];
    red[threadIdx.x] = s;
    __syncthreads();
    for (int o = 128; o > 0; o >>= 1) {
        if (threadIdx.x < o) red[threadIdx.x] += red[threadIdx.x + o];
        __syncthreads();
    }
    if (threadIdx.x == 0) g_obs[bt] = (red[0] > 1e-4f) ? 1.f : 0.f;
}

// ---------------- second gemm: out64x128 = Ts(64xK2) @ W(K2x128) ----------
template<int K2>
__device__ __forceinline__ void sgemm_TsW(
    const float* __restrict__ Ts, const float* __restrict__ W,
    int wm, int wn, int g, int tig, float acc2[2][4][4])
{
    #pragma unroll
    for (int mf = 0; mf < 2; mf++)
        #pragma unroll
        for (int nf = 0; nf < 4; nf++)
            #pragma unroll
            for (int e = 0; e < 4; e++) acc2[mf][nf][e] = 0.f;

    #pragma unroll
    for (int ks = 0; ks < K2 / 8; ks++) {
        const int kk = ks * 8;
        uint32_t a[2][4], bf[4][2];
        #pragma unroll
        for (int mf = 0; mf < 2; mf++) {
            int rb = wm * 32 + mf * 16 + g;
            a[mf][0] = __float_as_uint(Ts[(rb)     * TST + kk + tig]);
            a[mf][1] = __float_as_uint(Ts[(rb + 8) * TST + kk + tig]);
            a[mf][2] = __float_as_uint(Ts[(rb)     * TST + kk + tig + 4]);
            a[mf][3] = __float_as_uint(Ts[(rb + 8) * TST + kk + tig + 4]);
        }
        #pragma unroll
        for (int nf = 0; nf < 4; nf++) {
            int nb = wn * 32 + nf * 8 + g;
            bf[nf][0] = __float_as_uint(__ldg(W + (size_t)(kk + tig)     * 128 + nb));
            bf[nf][1] = __float_as_uint(__ldg(W + (size_t)(kk + tig + 4) * 128 + nb));
        }
        #pragma unroll
        for (int mf = 0; mf < 2; mf++)
            #pragma unroll
            for (int nf = 0; nf < 4; nf++)
                MMA_TF32(acc2[mf][nf], a[mf], bf[nf]);
    }
}

// ---------------- fused kernel: T = A@B, then epilogue second gemm --------
// NC = columns of B operand (128 or 192).
// EP: 0 = u = tanh(T@Wa+ba)                 -> Bout (tf32, ld=ldBout)
//     1 = hv1 = hin + (T@Wa+ba)*dt          -> dst fp32 + Bout tf32 (+ x*m copy to xdst)
//     2 = z = sig(T@Wa+ba) -> dst fp32;
//         r = sig(T@Wb+bb); rh = r*hin      -> Bout tf32; Tx=Ts[:,0:64] -> Txb
//     3 = Ts=[Tx, T]; c = tanh(Ts@Wa+ba);
//         h = hin + obs*z*(c-hin)           -> dst fp32 + Bout tf32
#define AS_STRIDE 36
#define AS_BUF (64 * AS_STRIDE)
#define FUSED_SMEM(NC) ((2 * AS_BUF + 2 * KC * ((NC) + 8)) * 4)

template<int NC, int EP>
__global__ __launch_bounds__(256) void fused_tc(
    const float* __restrict__ A, const float* __restrict__ Bop,
    const float* __restrict__ Wa, const float* __restrict__ Wb,
    const float* __restrict__ ba, const float* __restrict__ bb,
    float* __restrict__ dst, float* __restrict__ Bout, int ldBout,
    const float* __restrict__ hin,
    const float* __restrict__ zsr, const float* __restrict__ obsArr, int tIdx,
    const float* __restrict__ xv, const float* __restrict__ xm,
    float* __restrict__ Txb, float* __restrict__ xdst)
{
    extern __shared__ float sm[];
    constexpr int NF  = NC / 32;        // n-fragments per warp in main gemm
    constexpr int WNC = NC / 4;         // cols per wn slot
    constexpr int BST = NC + 8;         // B tile smem stride
    constexpr int BS_BUF = KC * BST;
    constexpr int K2 = (EP >= 2) ? 192 : 128;
    constexpr int CSH = (EP == 3) ? 64 : 0;   // Ts column shift for main acc

    float* AsBase = sm;
    float* BsBase = sm + 2 * AS_BUF;
    float* Ts     = sm;                 // aliased after main loop

    const int b = blockIdx.z;
    const int rowTile = blockIdx.x * 64;

    const int tid  = threadIdx.x;
    const int lane = tid & 31, warp = tid >> 5;
    const int wm = warp & 1, wn = warp >> 1;
    const int g  = lane >> 2, tig = lane & 3;

    const float* Ab = A + (size_t)b * NN * NN + (size_t)rowTile * NN;
    const float* Bb = Bop + (size_t)b * NN * NC;

    float acc[2][NF][4];
    #pragma unroll
    for (int mf = 0; mf < 2; mf++)
        #pragma unroll
        for (int nf = 0; nf < NF; nf++)
            #pragma unroll
            for (int e = 0; e < 4; e++) acc[mf][nf][e] = 0.f;

    auto prefetch = [&](int chunk, int buf) {
        float* Ad = AsBase + buf * AS_BUF;
        float* Bd = BsBase + buf * BS_BUF;
        const float* Ag = Ab + chunk * KC;
        const float* Bg = Bb + (size_t)chunk * KC * NC;
        #pragma unroll
        for (int l = 0; l < 2; l++) {
            int idx = tid + l * 256;
            int r = idx >> 3, kq = idx & 7;
            cpa16(Ad + r * AS_STRIDE + kq * 4, Ag + (size_t)r * NN + kq * 4);
        }
        #pragma unroll
        for (int l = 0; l < NF; l++) {
            int idx = tid + l * 256;
            int kk = idx / (NC / 4), cq = idx % (NC / 4);
            cpa16(Bd + kk * BST + cq * 4, Bg + (size_t)kk * NC + cq * 4);
        }
        asm volatile("cp.async.commit_group;");
    };

    prefetch(0, 0);
    for (int ch = 0; ch < NCHUNK; ch++) {
        int buf = ch & 1;
        if (ch + 1 < NCHUNK) {
            prefetch(ch + 1, buf ^ 1);
            asm volatile("cp.async.wait_group 1;");
        } else {
            asm volatile("cp.async.wait_group 0;");
        }
        __syncthreads();
        const float* Ad = AsBase + buf * AS_BUF;
        const float* Bd = BsBase + buf * BS_BUF;
        #pragma unroll
        for (int ks = 0; ks < 4; ks++) {
            const int kk = ks * 8;
            uint32_t a[2][4], bf[NF][2];
            #pragma unroll
            for (int mf = 0; mf < 2; mf++) {
                int rb = wm * 32 + mf * 16 + g;
                a[mf][0] = __float_as_uint(Ad[(rb)     * AS_STRIDE + kk + tig]);
                a[mf][1] = __float_as_uint(Ad[(rb + 8) * AS_STRIDE + kk + tig]);
                a[mf][2] = __float_as_uint(Ad[(rb)     * AS_STRIDE + kk + tig + 4]);
                a[mf][3] = __float_as_uint(Ad[(rb + 8) * AS_STRIDE + kk + tig + 4]);
            }
            #pragma unroll
            for (int nf = 0; nf < NF; nf++) {
                int nb = wn * WNC + nf * 8 + g;
                bf[nf][0] = __float_as_uint(Bd[(kk + tig)     * BST + nb]);
                bf[nf][1] = __float_as_uint(Bd[(kk + tig + 4) * BST + nb]);
            }
            #pragma unroll
            for (int mf = 0; mf < 2; mf++)
                #pragma unroll
                for (int nf = 0; nf < NF; nf++)
                    MMA_TF32(acc[mf][nf], a[mf], bf[nf]);
        }
        __syncthreads();
    }
    // stage T (tf32-rounded) into Ts smem (aliases main buffers; safe after sync)
    #pragma unroll
    for (int mf = 0; mf < 2; mf++)
        #pragma unroll
        for (int half = 0; half < 2; half++) {
            int row = wm * 32 + mf * 16 + g + half * 8;
            #pragma unroll
            for (int nf = 0; nf < NF; nf++) {
                int col = CSH + wn * WNC + nf * 8 + 2 * tig;
                Ts[row * TST + col]     = tf32r(acc[mf][nf][half * 2 + 0]);
                Ts[row * TST + col + 1] = tf32r(acc[mf][nf][half * 2 + 1]);
            }
        }
    if (EP == 3) {
        // load Tx (A@xm, 64 cols) into Ts[:, 0:64]
        for (int i = tid; i < 64 * 16; i += 256) {
            int row = i >> 4, c4 = (i & 15) * 4;
            *(float4*)&Ts[row * TST + c4] =
                *(const float4*)&Txb[((size_t)b * NN + rowTile + row) * 64 + c4];
        }
    }
    if (EP == 1 && xdst != nullptr) {
        // copy tf32(x*m) for this row tile into B1[:, 0:64]
        const float* xvb = xv + (((size_t)b * TT + tIdx) * NN + rowTile) * DIN;
        const float* xmb = xm + (((size_t)b * TT + tIdx) * NN + rowTile) * DIN;
        for (int i = tid; i < 64 * 16; i += 256) {
            int row = i >> 4, c4 = (i & 15) * 4;
            float4 v  = *(const float4*)(xvb + (size_t)row * DIN + c4);
            float4 mv = *(const float4*)(xmb + (size_t)row * DIN + c4);
            v.x = tf32r(v.x * mv.x); v.y = tf32r(v.y * mv.y);
            v.z = tf32r(v.z * mv.z); v.w = tf32r(v.w * mv.w);
            *(float4*)&xdst[((size_t)b * NN + rowTile + row) * ldBout + c4] = v;
        }
    }
    __syncthreads();

    if (EP == 2) {
        // export Tx = Ts[:, 0:64] (already tf32)
        for (int i = tid; i < 64 * 16; i += 256) {
            int row = i >> 4, c4 = (i & 15) * 4;
            *(float4*)&Txb[((size_t)b * NN + rowTile + row) * 64 + c4] =
                *(const float4*)&Ts[row * TST + c4];
        }
    }

    float acc2[2][4][4];
    // ---- first (or only) second-gemm: weights Wa ----
    sgemm_TsW<K2>(Ts, Wa, wm, wn, g, tig, acc2);

    const float ob = (EP == 3) ? obsArr[b * TT + tIdx] : 0.f;
    #pragma unroll
    for (int mf = 0; mf < 2; mf++)
        #pragma unroll
        for (int half = 0; half < 2; half++) {
            int row = wm * 32 + mf * 16 + g + half * 8;
            size_t gbase = ((size_t)b * NN + rowTile + row) * DR;
            size_t obase = ((size_t)b * NN + rowTile + row) * ldBout;
            #pragma unroll
            for (int nf = 0; nf < 4; nf++) {
                int col = wn * 32 + nf * 8 + 2 * tig;
                float s0 = acc2[mf][nf][half * 2 + 0] + ba[col];
                float s1 = acc2[mf][nf][half * 2 + 1] + ba[col + 1];
                if (EP == 0) {
                    *(float2*)(Bout + obase + col) =
                        make_float2(tf32r(tanhf(s0)), tf32r(tanhf(s1)));
                } else if (EP == 1) {
                    float v0 = hin[gbase + col]     + s0 * DT_VAL;
                    float v1 = hin[gbase + col + 1] + s1 * DT_VAL;
                    *(float2*)(dst + gbase + col) = make_float2(v0, v1);
                    *(float2*)(Bout + obase + col) =
                        make_float2(tf32r(v0), tf32r(v1));
                } else if (EP == 2) {
                    // z gate
                    float z0 = 1.f / (1.f + __expf(-s0));
                    float z1 = 1.f / (1.f + __expf(-s1));
                    *(float2*)(dst + gbase + col) = make_float2(z0, z1);
                } else {
                    float c0 = tanhf(s0), c1 = tanhf(s1);
                    float h0v = hin[gbase + col], h1v = hin[gbase + col + 1];
                    float v0 = h0v + ob * zsr[gbase + col]     * (c0 - h0v);
                    float v1 = h1v + ob * zsr[gbase + col + 1] * (c1 - h1v);
                    *(float2*)(dst + gbase + col) = make_float2(v0, v1);
                    *(float2*)(Bout + obase + col) =
                        make_float2(tf32r(v0), tf32r(v1));
                }
            }
        }

    if (EP == 2) {
        // ---- r gate: second gemm with Wb, then rh = r * hv1 -> Bout ----
        sgemm_TsW<K2>(Ts, Wb, wm, wn, g, tig, acc2);
        #pragma unroll
        for (int mf = 0; mf < 2; mf++)
            #pragma unroll
            for (int half = 0; half < 2; half++) {
                int row = wm * 32 + mf * 16 + g + half * 8;
                size_t gbase = ((size_t)b * NN + rowTile + row) * DR;
                size_t obase = ((size_t)b * NN + rowTile + row) * ldBout;
                #pragma unroll
                for (int nf = 0; nf < 4; nf++) {
                    int col = wn * 32 + nf * 8 + 2 * tig;
                    float s0 = acc2[mf][nf][half * 2 + 0] + bb[col];
                    float s1 = acc2[mf][nf][half * 2 + 1] + bb[col + 1];
                    float r0 = 1.f / (1.f + __expf(-s0));
                    float r1 = 1.f / (1.f + __expf(-s1));
                    float v0 = r0 * hin[gbase + col];
                    float v1 = r1 * hin[gbase + col + 1];
                    *(float2*)(Bout + obase + col) =
                        make_float2(tf32r(v0), tf32r(v1));
                }
            }
    }
}

// ---------------- output head: out[b,t-1] = hv1 @ Wo + bo (fp32) ----------
__global__ __launch_bounds__(256) void outproj_kernel(
    const float* __restrict__ hv1, const float* __restrict__ Wo,
    const float* __restrict__ bo, float* __restrict__ out, int t)
{
    __shared__ float Hs[KC][68];
    __shared__ float Ws[KC][68];
    int rowTile = blockIdx.x * 64;
    int b  = rowTile >> 10;
    int i0 = rowTile & (NN - 1);
    int tid = threadIdx.x;
    int tx = tid & 7, ty = tid >> 3;
    int c0 = tx * 8,  r0 = ty * 2;

    const float* hb = hv1 + ((size_t)b * NN + i0) * DR;

    float acc[2][8];
    #pragma unroll
    for (int i = 0; i < 2; i++)
        #pragma unroll
        for (int j = 0; j < 8; j++) acc[i][j] = 0.f;

    for (int k0 = 0; k0 < DR; k0 += KC) {
        #pragma unroll
        for (int l = 0; l < 2; l++) {
            int idx = tid + l * 256;
            int r = idx >> 3, k4 = idx & 7;
            float4 v = *(const float4*)(hb + (size_t)r * DR + k0 + k4 * 4);
            Hs[k4 * 4 + 0][r] = v.x;
            Hs[k4 * 4 + 1][r] = v.y;
            Hs[k4 * 4 + 2][r] = v.z;
            Hs[k4 * 4 + 3][r] = v.w;
        }
        #pragma unroll
        for (int l = 0; l < 2; l++) {
            int idx = tid + l * 256;
            int kk = idx >> 4, c4 = idx & 15;
            *(float4*)&Ws[kk][c4 * 4] =
                *(const float4*)(Wo + (size_t)(k0 + kk) * DIN + c4 * 4);
        }
        __syncthreads();
        #pragma unroll
        for (int kk = 0; kk < KC; kk++) {
            float a0 = Hs[kk][r0], a1 = Hs[kk][r0 + 1];
            float p[8];
            *(float4*)&p[0] = *(float4*)&Ws[kk][c0];
            *(float4*)&p[4] = *(float4*)&Ws[kk][c0 + 4];
            #pragma unroll
            for (int j = 0; j < 8; j++) {
                acc[0][j] = fmaf(a0, p[j], acc[0][j]);
                acc[1][j] = fmaf(a1, p[j], acc[1][j]);
            }
        }
        __syncthreads();
    }
    float bv[8];
    #pragma unroll
    for (int j = 0; j < 8; j++) bv[j] = bo[c0 + j];
    float* ob = out + (((size_t)b * (TT - 1) + (t - 1)) * NN + i0) * DIN;
    #pragma unroll
    for (int i = 0; i < 2; i++) {
        float* pr = ob + (size_t)(r0 + i) * DIN + c0;
        *(float4*)(pr + 0) = make_float4(acc[i][0] + bv[0], acc[i][1] + bv[1],
                                         acc[i][2] + bv[2], acc[i][3] + bv[3]);
        *(float4*)(pr + 4) = make_float4(acc[i][4] + bv[4], acc[i][5] + bv[5],
                                         acc[i][6] + bv[6], acc[i][7] + bv[7]);
    }
}

// ---------------- driver ----------------
extern "C" void kernel_launch(void* const* d_in, const int* in_sizes, int n_in,
                              void* d_out, int out_size)
{
    const float* values = (const float*)d_in[0];
    const float* masks  = (const float*)d_in[1];
    const float* A      = (const float*)d_in[2];
    const float* h0     = (const float*)d_in[3];
    const float* W0   = (const float*)d_in[4];
    const float* b0   = (const float*)d_in[5];
    const float* W1   = (const float*)d_in[6];
    const float* b1   = (const float*)d_in[7];
    const float* Wout = (const float*)d_in[8];
    const float* bout = (const float*)d_in[9];
    const float* Wz   = (const float*)d_in[10];
    const float* bz   = (const float*)d_in[11];
    const float* Wr   = (const float*)d_in[12];
    const float* br   = (const float*)d_in[13];
    const float* Wh   = (const float*)d_in[14];
    const float* bh   = (const float*)d_in[15];
    const float* Wo   = (const float*)d_in[16];
    const float* bo   = (const float*)d_in[17];
    float* out = (float*)d_out;

    float *h, *hv1, *z, *obs, *Atf, *Wtf, *Bh, *Bu1, *Bu2, *B1, *B2, *Tx;
    cudaGetSymbolAddress((void**)&h,   g_h);
    cudaGetSymbolAddress((void**)&hv1, g_hv1);
    cudaGetSymbolAddress((void**)&z,   g_z);
    cudaGetSymbolAddress((void**)&obs, g_obs);
    cudaGetSymbolAddress((void**)&Atf, g_Atf);
    cudaGetSymbolAddress((void**)&Wtf, g_Wtf);
    cudaGetSymbolAddress((void**)&Bh,  g_Bh);
    cudaGetSymbolAddress((void**)&Bu1, g_Bu1);
    cudaGetSymbolAddress((void**)&Bu2, g_Bu2);
    cudaGetSymbolAddress((void**)&B1,  g_B1);
    cudaGetSymbolAddress((void**)&B2,  g_B2);
    cudaGetSymbolAddress((void**)&Tx,  g_Tx);

    cudaFuncSetAttribute(fused_tc<128,0>, cudaFuncAttributeMaxDynamicSharedMemorySize, FUSED_SMEM(128));
    cudaFuncSetAttribute(fused_tc<128,1>, cudaFuncAttributeMaxDynamicSharedMemorySize, FUSED_SMEM(128));
    cudaFuncSetAttribute(fused_tc<192,2>, cudaFuncAttributeMaxDynamicSharedMemorySize, FUSED_SMEM(192));
    cudaFuncSetAttribute(fused_tc<128,3>, cudaFuncAttributeMaxDynamicSharedMemorySize, FUSED_SMEM(128));

    init_h_kernel<<<256, 256>>>(h0);
    round_A_kernel<<<512, 256>>>(A);
    round_W_kernel<<<128, 256>>>(W0, W1, Wout, Wz, Wr, Wh);
    obs_kernel<<<BB * TT, 256>>>(masks);

    const float* tW0   = Wtf + 0 * WSLOT;
    const float* tW1   = Wtf + 1 * WSLOT;
    const float* tWout = Wtf + 2 * WSLOT;
    const float* tWz   = Wtf + 3 * WSLOT;
    const float* tWr   = Wtf + 4 * WSLOT;
    const float* tWh   = Wtf + 5 * WSLOT;

    dim3 fg(16, 1, 8);

    // initial ODE-only step: h <- h + ode(h)*dt
    fused_tc<128,0><<<fg, 256, FUSED_SMEM(128)>>>(
        Atf, Bh, tW0, nullptr, b0, nullptr, nullptr, Bu1, 128,
        nullptr, nullptr, nullptr, 0, nullptr, nullptr, nullptr, nullptr);
    fused_tc<128,0><<<fg, 256, FUSED_SMEM(128)>>>(
        Atf, Bu1, tW1, nullptr, b1, nullptr, nullptr, Bu2, 128,
        nullptr, nullptr, nullptr, 0, nullptr, nullptr, nullptr, nullptr);
    fused_tc<128,1><<<fg, 256, FUSED_SMEM(128)>>>(
        Atf, Bu2, tWout, nullptr, bout, nullptr, h, Bh, 128,
        h, nullptr, nullptr, 0, nullptr, nullptr, nullptr, nullptr);

    for (int t = 0; t < TT; t++) {
        // ODE step: hv1 = h + ode(h)*dt ; also stage [x*m | hv1] into B1
        fused_tc<128,0><<<fg, 256, FUSED_SMEM(128)>>>(
            Atf, Bh, tW0, nullptr, b0, nullptr, nullptr, Bu1, 128,
            nullptr, nullptr, nullptr, 0, nullptr, nullptr, nullptr, nullptr);
        fused_tc<128,0><<<fg, 256, FUSED_SMEM(128)>>>(
            Atf, Bu1, tW1, nullptr, b1, nullptr, nullptr, Bu2, 128,
            nullptr, nullptr, nullptr, 0, nullptr, nullptr, nullptr, nullptr);
        fused_tc<128,1><<<fg, 256, FUSED_SMEM(128)>>>(
            Atf, Bu2, tWout, nullptr, bout, nullptr, hv1, B1 + 64, 192,
            h, nullptr, nullptr, t, values, masks, nullptr, B1);
        // gates: T = A@[xm,hv1]; z = sig(T@Wz), rh = sig(T@Wr)*hv1; Tx export
        fused_tc<192,2><<<fg, 256, FUSED_SMEM(192)>>>(
            Atf, B1, tWz, tWr, bz, br, z, B2, 128,
            hv1, nullptr, nullptr, t, nullptr, nullptr, Tx, nullptr);
        // candidate + blend: h = hv1 + obs*z*(tanh([Tx, A@rh]@Wh + bh) - hv1)
        fused_tc<128,3><<<fg, 256, FUSED_SMEM(128)>>>(
            Atf, B2, tWh, nullptr, bh, nullptr, h, Bh, 128,
            hv1, z, obs, t, nullptr, nullptr, Tx, nullptr);
        if (t >= 1)
            outproj_kernel<<<128, 256>>>(hv1, Wo, bo, out, t);
    }
}

// round 6
// speedup vs baseline: 2.2627x; 2.2627x over previous
#include <cuda_runtime.h>
#include <cuda_fp16.h>
#include <math.h>
#include <stdint.h>

#define BB 8
#define TT 32
#define NN 1024
#define DIN 64
#define DR 128
#define DT_VAL 0.25f
#define KC 32
#define NCHUNK (NN / KC)
#define WSLOT (192 * 128)
#define AST 40      // A smem stride (halves)
#define BST 136     // B smem stride (halves)

// ---------------- device scratch ----------------
__device__ float  g_h  [BB * NN * DR];
__device__ float  g_hv1[BB * NN * DR];
__device__ float  g_u  [BB * NN * DR];
__device__ float  g_z  [BB * NN * DR];
__device__ float  g_r  [BB * NN * DR];
__device__ float  g_obs[BB * TT];
__device__ __half g_Ah [BB * NN * NN];          // half A (16.7 MB)
__device__ __half g_Wh [6 * WSLOT];             // half weights
__device__ __half g_Woh[DR * DIN];              // half Wo
__device__ __half g_P  [BB * NN * 256];         // half projection buffer
__device__ __half g_hv1h[(size_t)BB * TT * NN * DR]; // half hv1 history (67 MB)

// ---------------- helpers ----------------
__device__ __forceinline__ void cpa16(void* s, const void* g) {
    uint32_t sa = (uint32_t)__cvta_generic_to_shared(s);
    asm volatile("cp.async.cg.shared.global [%0], [%1], 16;" :: "r"(sa), "l"(g));
}
__device__ __forceinline__ void ldsm4(uint32_t* r, uint32_t addr) {
    asm volatile("ldmatrix.sync.aligned.m8n8.x4.shared.b16 {%0,%1,%2,%3}, [%4];"
                 : "=r"(r[0]), "=r"(r[1]), "=r"(r[2]), "=r"(r[3]) : "r"(addr));
}
__device__ __forceinline__ void ldsm4t(uint32_t* r, uint32_t addr) {
    asm volatile("ldmatrix.sync.aligned.m8n8.x4.trans.shared.b16 {%0,%1,%2,%3}, [%4];"
                 : "=r"(r[0]), "=r"(r[1]), "=r"(r[2]), "=r"(r[3]) : "r"(addr));
}
#define MMA_F16(acc, a, b) \
    asm volatile( \
        "mma.sync.aligned.m16n8k16.row.col.f32.f16.f16.f32 " \
        "{%0,%1,%2,%3}, {%4,%5,%6,%7}, {%8,%9}, {%0,%1,%2,%3};" \
        : "+f"((acc)[0]), "+f"((acc)[1]), "+f"((acc)[2]), "+f"((acc)[3]) \
        : "r"((a)[0]), "r"((a)[1]), "r"((a)[2]), "r"((a)[3]), \
          "r"((b)[0]), "r"((b)[1]))

// ---------------- init h = broadcast(h0) ----------------
__global__ void init_h_kernel(const float* __restrict__ h0) {
    int idx = blockIdx.x * blockDim.x + threadIdx.x;
    const int total = BB * NN * DR;
    for (; idx < total; idx += gridDim.x * blockDim.x)
        g_h[idx] = h0[idx & (DR - 1)];
}

// ---------------- A -> half ----------------
__global__ void round_A_kernel(const float* __restrict__ A) {
    int idx = blockIdx.x * blockDim.x + threadIdx.x;
    const int total = BB * NN * NN;
    for (; idx < total; idx += gridDim.x * blockDim.x)
        g_Ah[idx] = __float2half(A[idx]);
}

// ---------------- weights -> half ----------------
__global__ void round_W_kernel(
    const float* __restrict__ W0, const float* __restrict__ W1,
    const float* __restrict__ Wout, const float* __restrict__ Wz,
    const float* __restrict__ Wr, const float* __restrict__ Wh,
    const float* __restrict__ Wo)
{
    const float* srcs[6] = {W0, W1, Wout, Wz, Wr, Wh};
    const int sizes[6] = {128*128, 128*128, 128*128, 192*128, 192*128, 192*128};
    for (int s = 0; s < 6; s++) {
        const float* src = srcs[s];
        __half* dst = g_Wh + s * WSLOT;
        for (int i = blockIdx.x * blockDim.x + threadIdx.x; i < sizes[s];
             i += gridDim.x * blockDim.x)
            dst[i] = __float2half(src[i]);
    }
    for (int i = blockIdx.x * blockDim.x + threadIdx.x; i < DR * DIN;
         i += gridDim.x * blockDim.x)
        g_Woh[i] = __float2half(Wo[i]);
}

// ---------------- obs[b,t] ----------------
__global__ void obs_kernel(const float* __restrict__ masks) {
    int bt = blockIdx.x;
    const float* m = masks + (size_t)bt * NN * DIN;
    float s = 0.f;
    for (int i = threadIdx.x; i < NN * DIN / 4; i += blockDim.x) {
        float4 v = ((const float4*)m)[i];
        s += fabsf(v.x) + fabsf(v.y) + fabsf(v.z) + fabsf(v.w);
    }
    __shared__ float red[256];
    red[threadIdx.x] = s;
    __syncthreads();
    for (int o = 128; o > 0; o >>= 1) {
        if (threadIdx.x < o) red[threadIdx.x] += red[threadIdx.x + o];
        __syncthreads();
    }
    if (threadIdx.x == 0) g_obs[bt] = (red[0] > 1e-4f) ? 1.f : 0.f;
}

// ---------------- fp16 projection: P = half([x*m | h or r*h] @ W) ----------
// 64 rows x 128 cols per CTA, 8 warps (2x4), warp tile 32x32 m16n8k16.
// grid.y selects (Wa, colOff 0) / (Wb, colOff 128).
template<bool HAS_X, bool HAS_R>
__global__ __launch_bounds__(256) void proj_h(
    const float* __restrict__ xv, const float* __restrict__ xm, int t,
    const float* __restrict__ h,  const float* __restrict__ rr,
    const __half* __restrict__ Wa, const __half* __restrict__ Wb,
    __half* __restrict__ P, int ldP, int Ktot)
{
    __shared__ __half Xs[64 * AST];
    __shared__ __half Ws[KC * BST];

    const int rowTile = blockIdx.x * 64;
    const int b  = rowTile >> 10;
    const int i0 = rowTile & (NN - 1);
    const int colOff = blockIdx.y * 128;
    const __half* W = blockIdx.y ? Wb : Wa;

    const int tid  = threadIdx.x;
    const int lane = tid & 31, warp = tid >> 5;
    const int wm = warp & 1, wn = warp >> 1;
    const int g  = lane >> 2, tig = lane & 3;
    const int quad = lane >> 3;
    const int lrow = (quad & 1) * 8 + (lane & 7);
    const int lcol = (quad >> 1) * 8;

    const int Kx = HAS_X ? DIN : 0;
    const float* hb  = h + ((size_t)b * NN + i0) * DR;
    const float* rb  = HAS_R ? rr + ((size_t)b * NN + i0) * DR : nullptr;
    const float* xvb = HAS_X ? xv + (((size_t)b * TT + t) * NN + i0) * DIN : nullptr;
    const float* xmb = HAS_X ? xm + (((size_t)b * TT + t) * NN + i0) * DIN : nullptr;

    const uint32_t sXs = (uint32_t)__cvta_generic_to_shared(Xs);
    const uint32_t sWs = (uint32_t)__cvta_generic_to_shared(Ws);

    float acc[2][4][4];
    #pragma unroll
    for (int mf = 0; mf < 2; mf++)
        #pragma unroll
        for (int nf = 0; nf < 4; nf++)
            #pragma unroll
            for (int e = 0; e < 4; e++) acc[mf][nf][e] = 0.f;

    for (int k0 = 0; k0 < Ktot; k0 += KC) {
        // stage activation tile 64x32: one 16B (8 half) store per thread
        {
            int r = tid >> 2, kq = tid & 3;
            float va[8];
            if (HAS_X && k0 < DIN) {
                float4 v0 = *(const float4*)(xvb + (size_t)r * DIN + k0 + kq * 8);
                float4 v1 = *(const float4*)(xvb + (size_t)r * DIN + k0 + kq * 8 + 4);
                float4 m0 = *(const float4*)(xmb + (size_t)r * DIN + k0 + kq * 8);
                float4 m1 = *(const float4*)(xmb + (size_t)r * DIN + k0 + kq * 8 + 4);
                va[0]=v0.x*m0.x; va[1]=v0.y*m0.y; va[2]=v0.z*m0.z; va[3]=v0.w*m0.w;
                va[4]=v1.x*m1.x; va[5]=v1.y*m1.y; va[6]=v1.z*m1.z; va[7]=v1.w*m1.w;
            } else {
                int kh = k0 - Kx;
                float4 v0 = *(const float4*)(hb + (size_t)r * DR + kh + kq * 8);
                float4 v1 = *(const float4*)(hb + (size_t)r * DR + kh + kq * 8 + 4);
                va[0]=v0.x; va[1]=v0.y; va[2]=v0.z; va[3]=v0.w;
                va[4]=v1.x; va[5]=v1.y; va[6]=v1.z; va[7]=v1.w;
                if (HAS_R) {
                    float4 r0 = *(const float4*)(rb + (size_t)r * DR + kh + kq * 8);
                    float4 r1 = *(const float4*)(rb + (size_t)r * DR + kh + kq * 8 + 4);
                    va[0]*=r0.x; va[1]*=r0.y; va[2]*=r0.z; va[3]*=r0.w;
                    va[4]*=r1.x; va[5]*=r1.y; va[6]*=r1.z; va[7]*=r1.w;
                }
            }
            union { uint4 u; __half2 h2[4]; } pk;
            #pragma unroll
            for (int q = 0; q < 4; q++)
                pk.h2[q] = __floats2half2_rn(va[2*q], va[2*q+1]);
            *(uint4*)&Xs[r * AST + kq * 8] = pk.u;
        }
        // stage W tile 32x128 (half, row-major)
        #pragma unroll
        for (int l = 0; l < 2; l++) {
            int idx = tid + l * 256;
            int kk2 = idx >> 4, cq = idx & 15;
            *(uint4*)&Ws[kk2 * BST + cq * 8] =
                *(const uint4*)(W + (size_t)(k0 + kk2) * 128 + cq * 8);
        }
        __syncthreads();
        #pragma unroll
        for (int ks = 0; ks < 2; ks++) {
            const int kk = ks * 16;
            uint32_t a[2][4], bq[2][4];
            #pragma unroll
            for (int mf = 0; mf < 2; mf++)
                ldsm4(a[mf], sXs + ((wm*32 + mf*16 + lrow) * AST + kk + lcol) * 2);
            #pragma unroll
            for (int p = 0; p < 2; p++)
                ldsm4t(bq[p], sWs + ((kk + lrow) * BST + wn*32 + p*16 + lcol) * 2);
            #pragma unroll
            for (int mf = 0; mf < 2; mf++) {
                MMA_F16(acc[mf][0], a[mf], &bq[0][0]);
                MMA_F16(acc[mf][1], a[mf], &bq[0][2]);
                MMA_F16(acc[mf][2], a[mf], &bq[1][0]);
                MMA_F16(acc[mf][3], a[mf], &bq[1][2]);
            }
        }
        __syncthreads();
    }
    __half* Pb = P + ((size_t)b * NN + i0) * ldP + colOff;
    #pragma unroll
    for (int mf = 0; mf < 2; mf++)
        #pragma unroll
        for (int half_ = 0; half_ < 2; half_++) {
            int row = wm*32 + mf*16 + g + half_*8;
            #pragma unroll
            for (int nf = 0; nf < 4; nf++) {
                int col = wn*32 + nf*8 + 2*tig;
                *(__half2*)(Pb + (size_t)row * ldP + col) =
                    __floats2half2_rn(acc[mf][nf][half_*2 + 0],
                                      acc[mf][nf][half_*2 + 1]);
            }
        }
}

// ---------------- fp16 A-multiply: G = A @ P, fused epilogue ---------------
// MODE: 0 u=tanh(G+b); 1 hv1=h+(G+b)*dt (+half history); 2 z/r=sig(G+b);
//       3 h=hv1+obs*z*(tanh(G+b)-hv1)
template<int MODE>
__global__ __launch_bounds__(256) void amult_h(
    const __half* __restrict__ A, const __half* __restrict__ P, int ldP,
    const float* __restrict__ bias0, const float* __restrict__ bias1,
    float* __restrict__ dst0, float* __restrict__ dst1,
    const float* __restrict__ hsrc, const float* __restrict__ zsrc,
    const float* __restrict__ obsArr, int tIdx, __half* __restrict__ hv1h)
{
    __shared__ __half As[2 * 64 * AST];
    __shared__ __half Bs[2 * KC * BST];

    const int b = blockIdx.z;
    const int rowTile = blockIdx.x * 64;
    const int cb = blockIdx.y;
    const int colOff = cb * 128;
    const float* bias = (MODE == 2 && cb == 1) ? bias1 : bias0;
    float* dst        = (MODE == 2 && cb == 1) ? dst1  : dst0;

    const int tid  = threadIdx.x;
    const int lane = tid & 31, warp = tid >> 5;
    const int wm = warp & 1, wn = warp >> 1;
    const int g  = lane >> 2, tig = lane & 3;
    const int quad = lane >> 3;
    const int lrow = (quad & 1) * 8 + (lane & 7);
    const int lcol = (quad >> 1) * 8;

    const __half* Ab = A + (size_t)b * NN * NN + (size_t)rowTile * NN;
    const __half* Pb = P + (size_t)b * NN * ldP + colOff;

    const uint32_t sAs = (uint32_t)__cvta_generic_to_shared(As);
    const uint32_t sBs = (uint32_t)__cvta_generic_to_shared(Bs);

    float acc[2][4][4];
    #pragma unroll
    for (int mf = 0; mf < 2; mf++)
        #pragma unroll
        for (int nf = 0; nf < 4; nf++)
            #pragma unroll
            for (int e = 0; e < 4; e++) acc[mf][nf][e] = 0.f;

    auto prefetch = [&](int chunk, int buf) {
        __half* Ad = As + buf * 64 * AST;
        __half* Bd = Bs + buf * KC * BST;
        {   // A: 64 rows x 32 halves, one cpa per thread
            int r = tid >> 2, kq = tid & 3;
            cpa16(Ad + r * AST + kq * 8, Ab + (size_t)r * NN + chunk * KC + kq * 8);
        }
        #pragma unroll
        for (int l = 0; l < 2; l++) {   // P: 32 rows x 128 halves
            int idx = tid + l * 256;
            int kk2 = idx >> 4, cq = idx & 15;
            cpa16(Bd + kk2 * BST + cq * 8,
                  Pb + (size_t)(chunk * KC + kk2) * ldP + cq * 8);
        }
        asm volatile("cp.async.commit_group;");
    };

    prefetch(0, 0);
    for (int ch = 0; ch < NCHUNK; ch++) {
        int buf = ch & 1;
        if (ch + 1 < NCHUNK) {
            prefetch(ch + 1, buf ^ 1);
            asm volatile("cp.async.wait_group 1;");
        } else {
            asm volatile("cp.async.wait_group 0;");
        }
        __syncthreads();
        const uint32_t aBase = sAs + buf * 64 * AST * 2;
        const uint32_t bBase = sBs + buf * KC * BST * 2;
        #pragma unroll
        for (int ks = 0; ks < 2; ks++) {
            const int kk = ks * 16;
            uint32_t a[2][4], bq[2][4];
            #pragma unroll
            for (int mf = 0; mf < 2; mf++)
                ldsm4(a[mf], aBase + ((wm*32 + mf*16 + lrow) * AST + kk + lcol) * 2);
            #pragma unroll
            for (int p = 0; p < 2; p++)
                ldsm4t(bq[p], bBase + ((kk + lrow) * BST + wn*32 + p*16 + lcol) * 2);
            #pragma unroll
            for (int mf = 0; mf < 2; mf++) {
                MMA_F16(acc[mf][0], a[mf], &bq[0][0]);
                MMA_F16(acc[mf][1], a[mf], &bq[0][2]);
                MMA_F16(acc[mf][2], a[mf], &bq[1][0]);
                MMA_F16(acc[mf][3], a[mf], &bq[1][2]);
            }
        }
        __syncthreads();
    }

    const float ob = (MODE == 3) ? obsArr[b * TT + tIdx] : 0.f;
    #pragma unroll
    for (int mf = 0; mf < 2; mf++)
        #pragma unroll
        for (int half_ = 0; half_ < 2; half_++) {
            int row = rowTile + wm*32 + mf*16 + g + half_*8;
            size_t base = ((size_t)b * NN + row) * DR;
            #pragma unroll
            for (int nf = 0; nf < 4; nf++) {
                int col = colOff + wn*32 + nf*8 + 2*tig;
                float v0 = acc[mf][nf][half_*2 + 0] + bias[col - colOff + 0];
                float v1 = acc[mf][nf][half_*2 + 1] + bias[col - colOff + 1];
                size_t idx = base + (col - colOff);
                if (MODE == 0) {
                    v0 = tanhf(v0); v1 = tanhf(v1);
                    *(float2*)(dst + idx) = make_float2(v0, v1);
                } else if (MODE == 1) {
                    v0 = hsrc[idx] + v0 * DT_VAL;
                    v1 = hsrc[idx + 1] + v1 * DT_VAL;
                    *(float2*)(dst + idx) = make_float2(v0, v1);
                    if (hv1h != nullptr) {
                        size_t hidx = (((size_t)b * TT + tIdx) * NN + row) * DR
                                      + (col - colOff);
                        *(__half2*)(hv1h + hidx) = __floats2half2_rn(v0, v1);
                    }
                } else if (MODE == 2) {
                    v0 = 1.f / (1.f + __expf(-v0));
                    v1 = 1.f / (1.f + __expf(-v1));
                    *(float2*)(dst + idx) = make_float2(v0, v1);
                } else {
                    float c0 = tanhf(v0), c1 = tanhf(v1);
                    float h0v = hsrc[idx], h1v = hsrc[idx + 1];
                    v0 = h0v + ob * zsrc[idx]     * (c0 - h0v);
                    v1 = h1v + ob * zsrc[idx + 1] * (c1 - h1v);
                    *(float2*)(dst + idx) = make_float2(v0, v1);
                }
            }
        }
}

// ---------------- batched output head: out[b,t-1] = hv1h[b,t] @ Wo + bo ----
// 64 n-rows x 64 cols, 4 warps (2x2), warp tile 32x32, K=128.
__global__ __launch_bounds__(128) void outgemm_h(
    const __half* __restrict__ hv1h, const __half* __restrict__ Wo,
    const float* __restrict__ bo, float* __restrict__ out)
{
    __shared__ __half As[64 * BST];
    __shared__ __half Ws[DR * 72];

    const int n0 = blockIdx.x * 64;
    const int t  = blockIdx.y + 1;
    const int b  = blockIdx.z;

    const int tid  = threadIdx.x;
    const int lane = tid & 31, warp = tid >> 5;
    const int wm = warp & 1, wn = warp >> 1;   // 2x2
    const int g  = lane >> 2, tig = lane & 3;
    const int quad = lane >> 3;
    const int lrow = (quad & 1) * 8 + (lane & 7);
    const int lcol = (quad >> 1) * 8;

    const __half* Hb = hv1h + (((size_t)b * TT + t) * NN + n0) * DR;

    // stage A 64x128 and W 128x64
    for (int i = tid; i < 64 * 16; i += 128) {
        int r = i >> 4, cq = i & 15;
        *(uint4*)&As[r * BST + cq * 8] = *(const uint4*)(Hb + (size_t)r * DR + cq * 8);
    }
    for (int i = tid; i < DR * 8; i += 128) {
        int r = i >> 3, cq = i & 7;
        *(uint4*)&Ws[r * 72 + cq * 8] = *(const uint4*)(Wo + (size_t)r * DIN + cq * 8);
    }
    __syncthreads();

    const uint32_t sAs = (uint32_t)__cvta_generic_to_shared(As);
    const uint32_t sWs = (uint32_t)__cvta_generic_to_shared(Ws);

    float acc[2][4][4];
    #pragma unroll
    for (int mf = 0; mf < 2; mf++)
        #pragma unroll
        for (int nf = 0; nf < 4; nf++)
            #pragma unroll
            for (int e = 0; e < 4; e++) acc[mf][nf][e] = 0.f;

    #pragma unroll
    for (int ks = 0; ks < 8; ks++) {
        const int kk = ks * 16;
        uint32_t a[2][4], bq[2][4];
        #pragma unroll
        for (int mf = 0; mf < 2; mf++)
            ldsm4(a[mf], sAs + ((wm*32 + mf*16 + lrow) * BST + kk + lcol) * 2);
        #pragma unroll
        for (int p = 0; p < 2; p++)
            ldsm4t(bq[p], sWs + ((kk + lrow) * 72 + wn*32 + p*16 + lcol) * 2);
        #pragma unroll
        for (int mf = 0; mf < 2; mf++) {
            MMA_F16(acc[mf][0], a[mf], &bq[0][0]);
            MMA_F16(acc[mf][1], a[mf], &bq[0][2]);
            MMA_F16(acc[mf][2], a[mf], &bq[1][0]);
            MMA_F16(acc[mf][3], a[mf], &bq[1][2]);
        }
    }

    float* ob = out + (((size_t)b * (TT - 1) + (t - 1)) * NN + n0) * DIN;
    #pragma unroll
    for (int mf = 0; mf < 2; mf++)
        #pragma unroll
        for (int half_ = 0; half_ < 2; half_++) {
            int row = wm*32 + mf*16 + g + half_*8;
            #pragma unroll
            for (int nf = 0; nf < 4; nf++) {
                int col = wn*32 + nf*8 + 2*tig;
                float v0 = acc[mf][nf][half_*2 + 0] + bo[col];
                float v1 = acc[mf][nf][half_*2 + 1] + bo[col + 1];
                *(float2*)(ob + (size_t)row * DIN + col) = make_float2(v0, v1);
            }
        }
}

// ---------------- driver ----------------
extern "C" void kernel_launch(void* const* d_in, const int* in_sizes, int n_in,
                              void* d_out, int out_size)
{
    const float* values = (const float*)d_in[0];
    const float* masks  = (const float*)d_in[1];
    const float* A      = (const float*)d_in[2];
    const float* h0     = (const float*)d_in[3];
    const float* W0   = (const float*)d_in[4];
    const float* b0   = (const float*)d_in[5];
    const float* W1   = (const float*)d_in[6];
    const float* b1   = (const float*)d_in[7];
    const float* Wout = (const float*)d_in[8];
    const float* bout = (const float*)d_in[9];
    const float* Wz   = (const float*)d_in[10];
    const float* bz   = (const float*)d_in[11];
    const float* Wr   = (const float*)d_in[12];
    const float* br   = (const float*)d_in[13];
    const float* Wh   = (const float*)d_in[14];
    const float* bh   = (const float*)d_in[15];
    const float* Wo   = (const float*)d_in[16];
    const float* bo   = (const float*)d_in[17];
    float* out = (float*)d_out;

    float *h, *hv1, *u, *z, *r, *obs;
    __half *Ah, *Wh6, *Woh, *P, *hv1h;
    cudaGetSymbolAddress((void**)&h,    g_h);
    cudaGetSymbolAddress((void**)&hv1,  g_hv1);
    cudaGetSymbolAddress((void**)&u,    g_u);
    cudaGetSymbolAddress((void**)&z,    g_z);
    cudaGetSymbolAddress((void**)&r,    g_r);
    cudaGetSymbolAddress((void**)&obs,  g_obs);
    cudaGetSymbolAddress((void**)&Ah,   g_Ah);
    cudaGetSymbolAddress((void**)&Wh6,  g_Wh);
    cudaGetSymbolAddress((void**)&Woh,  g_Woh);
    cudaGetSymbolAddress((void**)&P,    g_P);
    cudaGetSymbolAddress((void**)&hv1h, g_hv1h);

    init_h_kernel<<<256, 256>>>(h0);
    round_A_kernel<<<512, 256>>>(A);
    round_W_kernel<<<128, 256>>>(W0, W1, Wout, Wz, Wr, Wh, Wo);
    obs_kernel<<<BB * TT, 256>>>(masks);

    const __half* tW0   = Wh6 + 0 * WSLOT;
    const __half* tW1   = Wh6 + 1 * WSLOT;
    const __half* tWout = Wh6 + 2 * WSLOT;
    const __half* tWz   = Wh6 + 3 * WSLOT;
    const __half* tWr   = Wh6 + 4 * WSLOT;
    const __half* tWh   = Wh6 + 5 * WSLOT;

    dim3 ag(16, 1, 8), ag2(16, 2, 8);
    dim3 pg(128, 1, 1), pg2(128, 2, 1);

    auto ode_step = [&](const float* hin, float* dst, __half* histSlot, int t) {
        proj_h<false, false><<<pg, 256>>>(nullptr, nullptr, 0, hin, nullptr,
                                          tW0, nullptr, P, 128, 128);
        amult_h<0><<<ag, 256>>>(Ah, P, 128, b0, nullptr, u, nullptr,
                                nullptr, nullptr, nullptr, 0, nullptr);
        proj_h<false, false><<<pg, 256>>>(nullptr, nullptr, 0, u, nullptr,
                                          tW1, nullptr, P, 128, 128);
        amult_h<0><<<ag, 256>>>(Ah, P, 128, b1, nullptr, u, nullptr,
                                nullptr, nullptr, nullptr, 0, nullptr);
        proj_h<false, false><<<pg, 256>>>(nullptr, nullptr, 0, u, nullptr,
                                          tWout, nullptr, P, 128, 128);
        amult_h<1><<<ag, 256>>>(Ah, P, 128, bout, nullptr, dst, nullptr,
                                hin, nullptr, nullptr, t, histSlot);
    };

    // iteration 0: ODE-only update of h (no history)
    ode_step(h, h, nullptr, 0);

    for (int t = 0; t < TT; t++) {
        ode_step(h, hv1, hv1h, t);             // hv1 = h + ode(h)*dt
        // gates z, r on concat([x, hv1]); one launch, grid.y picks Wz/Wr
        proj_h<true, false><<<pg2, 256>>>(values, masks, t, hv1, nullptr,
                                          tWz, tWr, P, 256, 192);
        amult_h<2><<<ag2, 256>>>(Ah, P, 256, bz, br, z, r,
                                 nullptr, nullptr, nullptr, 0, nullptr);
        // candidate on concat([x, r*hv1]) then final blend into h
        proj_h<true, true><<<pg, 256>>>(values, masks, t, hv1, r,
                                        tWh, nullptr, P, 128, 192);
        amult_h<3><<<ag, 256>>>(Ah, P, 128, bh, nullptr, h, nullptr,
                                hv1, z, obs, t, nullptr);
    }

    // batched output head over stored hv1 history (t = 1..31)
    dim3 og(NN / 64, TT - 1, BB);
    outgemm_h<<<og, 128>>>(hv1h, Woh, bo, out);
}